// round 2
// baseline (speedup 1.0000x reference)
#include <cuda_runtime.h>
#include <math.h>

// ---------------- problem constants ----------------
#define MM   2048      // graph nodes / rows of cost
#define NN   2048      // devices / cols of cost
#define EE   16384     // edges
#define DIN  32
#define HID  64
#define DD   96
#define NHH  4
#define HDD  24
#define FFDD 256
#define LL   4
#define MP1  2049      // M+1 (with dustbin)
#define SINK_ITERS 100
#define LAMBDA 0.1f

// ---------------- device scratch (no allocations allowed) ----------------
__device__ float g_Cp [MP1*MP1];
__device__ float g_CpT[MP1*MP1];
__device__ float g_t    [MM*DD];
__device__ float g_qkv  [MM*3*DD];
__device__ float g_attno[MM*DD];
__device__ float g_proj [MM*DD];
__device__ float g_ff1  [MM*FFDD];
__device__ float g_cg   [MM*DD];
__device__ float g_match[MM*DD];
__device__ float g_agg  [MM*HID];
__device__ float g_h    [MM*HID];
__device__ float g_deg[MM];
__device__ float g_nrm[MM];
__device__ float g_u[MP1];
__device__ float g_v[MP1];
__device__ float g_lmu[MP1];
__device__ float g_lnu[MP1];
__device__ float g_v0[MM];
__device__ float g_v1[NN];
__device__ int   g_i0[MM];
__device__ int   g_i1[NN];
__device__ float g_ms0[MM];

// ---------------- generic tiled GEMM: C = op(alpha * A @ B^T + bias) ----------------
// A: [Mm,Kk] row-major.  transB=0: B stored [Nn,Kk] (i.e. C=A@B^T).
//                        transB=1: B stored [Kk,Nn] (i.e. C=A@B).
// mode: 0 none, 1 relu, 2 abs.  Kk must be a multiple of 16 (all our K are).
__global__ void gemm_kernel(const float* __restrict__ A, const float* __restrict__ B,
                            const float* __restrict__ bias, float* __restrict__ C,
                            int Mm, int Nn, int Kk, int ldc,
                            int transB, int mode, float alpha)
{
    __shared__ float As[16][64];
    __shared__ float Bs[16][64];
    int tid = threadIdx.x;
    int m0 = blockIdx.y * 64, n0 = blockIdx.x * 64;
    int tm = tid >> 4, tn = tid & 15;
    float acc[4][4] = {};
    for (int k0 = 0; k0 < Kk; k0 += 16) {
        #pragma unroll
        for (int r = 0; r < 4; r++) {
            int idx = tid + r * 256;
            int ar = idx >> 4, ac = idx & 15;
            int gm = m0 + ar, gk = k0 + ac;
            As[ac][ar] = (gm < Mm && gk < Kk) ? A[(size_t)gm * Kk + gk] : 0.f;
        }
        #pragma unroll
        for (int r = 0; r < 4; r++) {
            int idx = tid + r * 256;
            if (transB) {
                int bk = idx >> 6, bn = idx & 63;
                int gk = k0 + bk, gn = n0 + bn;
                Bs[bk][bn] = (gn < Nn && gk < Kk) ? B[(size_t)gk * Nn + gn] : 0.f;
            } else {
                int br = idx >> 4, bc = idx & 15;
                int gn = n0 + br, gk = k0 + bc;
                Bs[bc][br] = (gn < Nn && gk < Kk) ? B[(size_t)gn * Kk + gk] : 0.f;
            }
        }
        __syncthreads();
        #pragma unroll
        for (int kk = 0; kk < 16; kk++) {
            float ar[4], br[4];
            #pragma unroll
            for (int i = 0; i < 4; i++) ar[i] = As[kk][tm*4+i];
            #pragma unroll
            for (int j = 0; j < 4; j++) br[j] = Bs[kk][tn*4+j];
            #pragma unroll
            for (int i = 0; i < 4; i++)
                #pragma unroll
                for (int j = 0; j < 4; j++)
                    acc[i][j] += ar[i] * br[j];
        }
        __syncthreads();
    }
    #pragma unroll
    for (int i = 0; i < 4; i++) {
        int gm = m0 + tm*4 + i;
        if (gm >= Mm) continue;
        #pragma unroll
        for (int j = 0; j < 4; j++) {
            int gn = n0 + tn*4 + j;
            if (gn >= Nn) continue;
            float v = acc[i][j] * alpha;
            if (bias) v += bias[gn];
            if (mode == 1) v = fmaxf(v, 0.f);
            else if (mode == 2) v = fabsf(v);
            C[(size_t)gm * ldc + gn] = v;
        }
    }
}

// ---------------- fused MHA: online-softmax, warp per query ----------------
// qkv layout: [2048, 288] = [q(4x24) | k(4x24) | v(4x24)] per row.
#define ATT_TS 64
__global__ void attn_kernel(const float* __restrict__ qkv, float* __restrict__ out)
{
    __shared__ float sK[ATT_TS][25];
    __shared__ float sV[ATT_TS][25];
    int head = blockIdx.y;
    int warp = threadIdx.x >> 5, lane = threadIdx.x & 31;
    int qi = blockIdx.x * 16 + warp;
    const float* qrow = qkv + (size_t)qi * 288 + head * 24;
    float q[24];
    #pragma unroll
    for (int c = 0; c < 24; c++) q[c] = qrow[c];
    float m = -1e30f, l = 0.f, o[24];
    #pragma unroll
    for (int c = 0; c < 24; c++) o[c] = 0.f;
    const float rscale = 0.2041241452319315f;  // 1/sqrt(24)
    for (int t0 = 0; t0 < 2048; t0 += ATT_TS) {
        __syncthreads();
        for (int idx = threadIdx.x; idx < ATT_TS*24; idx += 512) {
            int key = idx / 24, c = idx % 24;
            const float* kvrow = qkv + (size_t)(t0 + key) * 288 + head * 24;
            sK[key][c] = kvrow[96 + c];
            sV[key][c] = kvrow[192 + c];
        }
        __syncthreads();
        #pragma unroll
        for (int r = 0; r < ATT_TS/32; r++) {
            int kk = lane + r * 32;
            float s = 0.f;
            #pragma unroll
            for (int c = 0; c < 24; c++) s += q[c] * sK[kk][c];
            s *= rscale;
            float nm = fmaxf(m, s);
            float corr = __expf(m - nm);
            float p    = __expf(s - nm);
            l = l * corr + p;
            #pragma unroll
            for (int c = 0; c < 24; c++) o[c] = o[c] * corr + p * sV[kk][c];
            m = nm;
        }
    }
    float mw = m;
    #pragma unroll
    for (int off = 16; off; off >>= 1) mw = fmaxf(mw, __shfl_xor_sync(0xffffffffu, mw, off));
    float cf = __expf(m - mw);
    l *= cf;
    #pragma unroll
    for (int c = 0; c < 24; c++) o[c] *= cf;
    #pragma unroll
    for (int off = 16; off; off >>= 1) l += __shfl_xor_sync(0xffffffffu, l, off);
    #pragma unroll
    for (int c = 0; c < 24; c++)
        #pragma unroll
        for (int off = 16; off; off >>= 1) o[c] += __shfl_xor_sync(0xffffffffu, o[c], off);
    if (lane == 0) {
        float inv = 1.f / l;
        #pragma unroll
        for (int c = 0; c < 24; c++) out[(size_t)qi * 96 + head * 24 + c] = o[c] * inv;
    }
}

// ---------------- LayerNorm of (t + delta), in-place into t ----------------
__global__ void ln_kernel(float* __restrict__ t, const float* __restrict__ delta,
                          const float* __restrict__ g, const float* __restrict__ b)
{
    __shared__ float sr[96];
    int i = blockIdx.x, c = threadIdx.x;
    float x = t[(size_t)i*96 + c] + delta[(size_t)i*96 + c];
    sr[c] = x;
    __syncthreads();
    for (int s = 64; s > 0; s >>= 1) { if (c < s && c + s < 96) sr[c] += sr[c+s]; __syncthreads(); }
    float mu = sr[0] / 96.f;
    __syncthreads();
    float d = x - mu;
    sr[c] = d * d;
    __syncthreads();
    for (int s = 64; s > 0; s >>= 1) { if (c < s && c + s < 96) sr[c] += sr[c+s]; __syncthreads(); }
    float var = sr[0] / 96.f;
    t[(size_t)i*96 + c] = d * rsqrtf(var + 1e-5f) * g[c] + b[c];
}

// ---------------- GCN propagation ----------------
__global__ void k_deg_init() { int i = blockIdx.x*blockDim.x + threadIdx.x; if (i < MM) g_deg[i] = 1.f; }
__global__ void k_deg_acc(const int* __restrict__ ei) {
    int e = blockIdx.x*blockDim.x + threadIdx.x;
    if (e < EE) atomicAdd(&g_deg[ei[EE + e]], 1.f);
}
__global__ void k_nrm() { int i = blockIdx.x*blockDim.x + threadIdx.x; if (i < MM) g_nrm[i] = rsqrtf(g_deg[i]); }
__global__ void k_prop_init(const float* __restrict__ h, int F) {
    int idx = blockIdx.x*blockDim.x + threadIdx.x;
    if (idx < MM * F) g_agg[idx] = h[idx] * g_nrm[idx / F];   // self loop
}
__global__ void k_prop_edge(const float* __restrict__ h, const int* __restrict__ ei, int F) {
    int idx = blockIdx.x*blockDim.x + threadIdx.x;
    if (idx < EE * F) {
        int e = idx / F, f = idx % F;
        int s = ei[e], d = ei[EE + e];
        atomicAdd(&g_agg[(size_t)d * F + f], h[(size_t)s * F + f] * g_nrm[s]);
    }
}
__global__ void k_prop_scale(int F) {
    int idx = blockIdx.x*blockDim.x + threadIdx.x;
    if (idx < MM * F) g_agg[idx] *= g_nrm[idx / F];
}

// ---------------- Sinkhorn ----------------
__global__ void k_bins(const float* __restrict__ binp) {
    int i = blockIdx.x*blockDim.x + threadIdx.x;
    if (i < MP1) {
        float bl = binp[0] / LAMBDA;
        g_Cp [(size_t)i*MP1 + (MP1-1)] = bl;
        g_Cp [(size_t)(MP1-1)*MP1 + i] = bl;
        g_CpT[(size_t)i*MP1 + (MP1-1)] = bl;
        g_CpT[(size_t)(MP1-1)*MP1 + i] = bl;
    }
}
__global__ void k_sink_init() {
    int i = blockIdx.x*blockDim.x + threadIdx.x;
    if (i < MP1) {
        float norm = -logf((float)(MM + NN));
        g_u[i] = 0.f; g_v[i] = 0.f;
        g_lmu[i] = (i < MM) ? norm : (logf((float)NN) + norm);
        g_lnu[i] = (i < NN) ? norm : (logf((float)MM) + norm);
    }
}
// out[i] = lmarg[i] - logsumexp_j(Cmat[i,j] + addv[j]);  one block per row.
__global__ void lse_kernel(const float* __restrict__ Cm, const float* __restrict__ addv,
                           const float* __restrict__ lmarg, float* __restrict__ outv)
{
    __shared__ float sx[MP1];
    __shared__ float sr[256];
    int i = blockIdx.x, tid = threadIdx.x;
    const float* row = Cm + (size_t)i * MP1;
    float lm = -1e30f;
    for (int j = tid; j < MP1; j += 256) {
        float x = row[j] + addv[j];
        sx[j] = x;
        lm = fmaxf(lm, x);
    }
    sr[tid] = lm; __syncthreads();
    for (int s = 128; s > 0; s >>= 1) { if (tid < s) sr[tid] = fmaxf(sr[tid], sr[tid+s]); __syncthreads(); }
    float m = sr[0];
    __syncthreads();
    float ls = 0.f;
    for (int j = tid; j < MP1; j += 256) ls += __expf(sx[j] - m);
    sr[tid] = ls; __syncthreads();
    for (int s = 128; s > 0; s >>= 1) { if (tid < s) sr[tid] += sr[tid+s]; __syncthreads(); }
    if (tid == 0) outv[i] = lmarg[i] - (m + __logf(sr[0]));
}

// ---------------- outputs ----------------
__global__ void k_scores(float* __restrict__ out) {
    int j = blockIdx.x*blockDim.x + threadIdx.x;
    int i = blockIdx.y;
    if (j < MP1) {
        const float norm = -8.317766166719343f; // -log(4096)
        out[(size_t)i*MP1 + j] = g_Cp[(size_t)i*MP1 + j] + g_u[i] + g_v[j] - norm;
    }
}
__global__ void k_rowstat(float* __restrict__ ent_out) {
    __shared__ float sv[256]; __shared__ int si[256]; __shared__ float se[256];
    int i = blockIdx.x, tid = threadIdx.x;
    const float norm = -8.317766166719343f;
    float ui = g_u[i];
    float bv = -1e30f; int bi = 0; float ent = 0.f;
    for (int j = tid; j < NN; j += 256) {
        float x = g_Cp[(size_t)i*MP1 + j] + ui + g_v[j] - norm;
        if (x > bv) { bv = x; bi = j; }
        ent += x * __expf(x);
    }
    sv[tid] = bv; si[tid] = bi; se[tid] = ent; __syncthreads();
    for (int s = 128; s > 0; s >>= 1) {
        if (tid < s) {
            if (sv[tid+s] > sv[tid] || (sv[tid+s] == sv[tid] && si[tid+s] < si[tid])) {
                sv[tid] = sv[tid+s]; si[tid] = si[tid+s];
            }
            se[tid] += se[tid+s];
        }
        __syncthreads();
    }
    if (tid == 0) { g_v0[i] = sv[0]; g_i0[i] = si[0]; ent_out[i] = se[0]; }
}
__global__ void k_colstat() {
    __shared__ float sv[256]; __shared__ int si[256];
    int j = blockIdx.x, tid = threadIdx.x;
    const float norm = -8.317766166719343f;
    float vj = g_v[j];
    float bv = -1e30f; int bi = 0;
    for (int i = tid; i < MM; i += 256) {
        float x = g_CpT[(size_t)j*MP1 + i] + g_u[i] + vj - norm;
        if (x > bv) { bv = x; bi = i; }
    }
    sv[tid] = bv; si[tid] = bi; __syncthreads();
    for (int s = 128; s > 0; s >>= 1) {
        if (tid < s) {
            if (sv[tid+s] > sv[tid] || (sv[tid+s] == sv[tid] && si[tid+s] < si[tid])) {
                sv[tid] = sv[tid+s]; si[tid] = si[tid+s];
            }
        }
        __syncthreads();
    }
    if (tid == 0) { g_v1[j] = sv[0]; g_i1[j] = si[0]; }
}
__global__ void k_mutual0(float* __restrict__ ms0_out) {
    int i = blockIdx.x*blockDim.x + threadIdx.x;
    if (i < MM) {
        int j = g_i0[i];
        float val = (g_i1[j] == i) ? __expf(g_v0[i]) : 0.f;
        g_ms0[i] = val;
        ms0_out[i] = val;
    }
}
__global__ void k_mutual1(float* __restrict__ ms1_out) {
    int j = blockIdx.x*blockDim.x + threadIdx.x;
    if (j < NN) {
        int i = g_i1[j];
        ms1_out[j] = (g_i0[i] == j) ? g_ms0[i] : 0.f;
    }
}

// ---------------- host side ----------------
static float* sym(const void* p) { return (float*)p; }

extern "C" void kernel_launch(void* const* d_in, const int* in_sizes, int n_in,
                              void* d_out, int out_size)
{
    const float* x        = (const float*)d_in[0];
    const int*   ei       = (const int*)  d_in[1];
    const float* devfeat  = (const float*)d_in[2];
    const float* gnn_w1   = (const float*)d_in[3];
    const float* gnn_b1   = (const float*)d_in[4];
    const float* gnn_w2   = (const float*)d_in[5];
    const float* gnn_b2   = (const float*)d_in[6];
    const float* sa_w     = (const float*)d_in[7];
    const float* sa_b     = (const float*)d_in[8];
    const float* sa_ow    = (const float*)d_in[9];
    const float* sa_ob    = (const float*)d_in[10];
    const float* ca_w     = (const float*)d_in[11];
    const float* ca_b     = (const float*)d_in[12];
    const float* ca_ow    = (const float*)d_in[13];
    const float* ca_ob    = (const float*)d_in[14];
    const float* ln_g     = (const float*)d_in[15];
    const float* ln_b     = (const float*)d_in[16];
    const float* ff_w1    = (const float*)d_in[17];
    const float* ff_b1    = (const float*)d_in[18];
    const float* ff_w2    = (const float*)d_in[19];
    const float* ff_b2    = (const float*)d_in[20];
    const float* mf_w     = (const float*)d_in[21];
    const float* mf_b     = (const float*)d_in[22];
    const float* bin      = (const float*)d_in[23];
    float* out = (float*)d_out;

    void *pv;
    cudaGetSymbolAddress(&pv, g_Cp);    float* p_Cp    = sym(pv);
    cudaGetSymbolAddress(&pv, g_CpT);   float* p_CpT   = sym(pv);
    cudaGetSymbolAddress(&pv, g_t);     float* p_t     = sym(pv);
    cudaGetSymbolAddress(&pv, g_qkv);   float* p_qkv   = sym(pv);
    cudaGetSymbolAddress(&pv, g_attno); float* p_attno = sym(pv);
    cudaGetSymbolAddress(&pv, g_proj);  float* p_proj  = sym(pv);
    cudaGetSymbolAddress(&pv, g_ff1);   float* p_ff1   = sym(pv);
    cudaGetSymbolAddress(&pv, g_cg);    float* p_cg    = sym(pv);
    cudaGetSymbolAddress(&pv, g_match); float* p_match = sym(pv);
    cudaGetSymbolAddress(&pv, g_agg);   float* p_agg   = sym(pv);
    cudaGetSymbolAddress(&pv, g_h);     float* p_h     = sym(pv);
    cudaGetSymbolAddress(&pv, g_u);     float* p_u     = sym(pv);
    cudaGetSymbolAddress(&pv, g_v);     float* p_v     = sym(pv);
    cudaGetSymbolAddress(&pv, g_lmu);   float* p_lmu   = sym(pv);
    cudaGetSymbolAddress(&pv, g_lnu);   float* p_lnu   = sym(pv);

    auto gemm = [&](const float* A, const float* B, const float* bias, float* C,
                    int Mm, int Nn, int Kk, int ldc, int transB, int mode, float alpha) {
        dim3 grid((Nn + 63) / 64, (Mm + 63) / 64);
        gemm_kernel<<<grid, 256>>>(A, B, bias, C, Mm, Nn, Kk, ldc, transB, mode, alpha);
    };

    // ---- GCN ----
    k_deg_init<<<(MM+255)/256, 256>>>();
    k_deg_acc<<<(EE+255)/256, 256>>>(ei);
    k_nrm<<<(MM+255)/256, 256>>>();

    k_prop_init <<<(MM*DIN+255)/256, 256>>>(x, DIN);
    k_prop_edge <<<(EE*DIN+255)/256, 256>>>(x, ei, DIN);
    k_prop_scale<<<(MM*DIN+255)/256, 256>>>(DIN);
    gemm(p_agg, gnn_w1, gnn_b1, p_h, MM, HID, DIN, HID, 1, 0, 1.f);

    k_prop_init <<<(MM*HID+255)/256, 256>>>(p_h, HID);
    k_prop_edge <<<(EE*HID+255)/256, 256>>>(p_h, ei, HID);
    k_prop_scale<<<(MM*HID+255)/256, 256>>>(HID);
    gemm(p_agg, gnn_w2, gnn_b2, p_cg, MM, DD, HID, DD, 1, 0, 1.f);

    // ---- transformer ----
    cudaMemcpyAsync(p_t, devfeat, (size_t)MM*DD*sizeof(float), cudaMemcpyDeviceToDevice);
    for (int l = 0; l < LL; l++) {
        // self-attention
        gemm(p_t, sa_w + (size_t)l*288*96, sa_b + l*288, p_qkv, MM, 288, 96, 288, 0, 0, 1.f);
        attn_kernel<<<dim3(128, NHH), 512>>>(p_qkv, p_attno);
        gemm(p_attno, sa_ow + (size_t)l*96*96, sa_ob + l*96, p_proj, MM, 96, 96, 96, 0, 0, 1.f);
        ln_kernel<<<MM, 96>>>(p_t, p_proj, ln_g + (l*3+0)*96, ln_b + (l*3+0)*96);
        // cross-attention: q from t, k/v from cg
        gemm(p_t,  ca_w + (size_t)l*288*96,         ca_b + l*288,      p_qkv,      MM,  96, 96, 288, 0, 0, 1.f);
        gemm(p_cg, ca_w + (size_t)l*288*96 + 96*96, ca_b + l*288 + 96, p_qkv + 96, MM, 192, 96, 288, 0, 0, 1.f);
        attn_kernel<<<dim3(128, NHH), 512>>>(p_qkv, p_attno);
        gemm(p_attno, ca_ow + (size_t)l*96*96, ca_ob + l*96, p_proj, MM, 96, 96, 96, 0, 0, 1.f);
        ln_kernel<<<MM, 96>>>(p_t, p_proj, ln_g + (l*3+1)*96, ln_b + (l*3+1)*96);
        // FFN
        gemm(p_t,   ff_w1 + (size_t)l*256*96, ff_b1 + l*256, p_ff1,  MM, 256,  96, 256, 0, 1, 1.f);
        gemm(p_ff1, ff_w2 + (size_t)l*96*256, ff_b2 + l*96,  p_proj, MM,  96, 256,  96, 0, 0, 1.f);
        ln_kernel<<<MM, 96>>>(p_t, p_proj, ln_g + (l*3+2)*96, ln_b + (l*3+2)*96);
    }

    // ---- cost matrix (and transpose) ----
    gemm(p_t, mf_w, mf_b, p_match, MM, 96, 96, 96, 1, 0, 1.f);
    float alpha = 1.f / (sqrtf(96.f) * LAMBDA);
    gemm(p_cg,    p_match, 0, p_Cp,  MM, NN, 96, MP1, 0, 2, alpha);
    gemm(p_match, p_cg,    0, p_CpT, NN, MM, 96, MP1, 0, 2, alpha);
    k_bins<<<(MP1+255)/256, 256>>>(bin);
    k_sink_init<<<(MP1+255)/256, 256>>>();

    // ---- Sinkhorn ----
    for (int it = 0; it < SINK_ITERS; it++) {
        lse_kernel<<<MP1, 256>>>(p_Cp,  p_v, p_lmu, p_u);
        lse_kernel<<<MP1, 256>>>(p_CpT, p_u, p_lnu, p_v);
    }

    // ---- outputs: scores | entropy | mscores0 | mscores1 ----
    size_t off_ent = (size_t)MP1 * MP1;
    k_scores<<<dim3((MP1+255)/256, MP1), 256>>>(out);
    k_rowstat<<<MM, 256>>>(out + off_ent);
    k_colstat<<<NN, 256>>>();
    k_mutual0<<<(MM+255)/256, 256>>>(out + off_ent + MM);
    k_mutual1<<<(NN+255)/256, 256>>>(out + off_ent + MM + NN);
}